// round 11
// baseline (speedup 1.0000x reference)
#include <cuda_runtime.h>
#include <cuda_fp16.h>
#include <cstdint>

#define N_NODES 30000
#define N_PAD   30080           // 235 * 128
#define N_EDGES 240000
#define DM 256
#define QKVW 768
#define NGRAPH 64
#define NLAYER 3
#define SCAN_B  30              // ceil(30000/1024)

// GEMM smem layout (fp16 elems per stage): Ah 128x40, Bh 32x136
#define ASTRIDE 40
#define BSTRIDE 136
#define OFF_BH  5120
#define STAGE_E 9472            // elems per stage (18944 B); 4 stages = 75776 B

// ---------------- scratch ----------------
__device__ __align__(128) __half g_qh[N_NODES * DM];       // fp16 q
__device__ __align__(128) __half g_kv[N_NODES * 512];      // fp16 k | v
__device__ __align__(128) float  g_pool[NGRAPH * DM];
__device__ __align__(128) float  g_cnt[NGRAPH];
__device__ __align__(128) __half g_xh[N_PAD * DM];         // fp16 activations (row-major)
__device__ __align__(128) __half g_wh[NLAYER * DM * QKVW]; // fp16 W, [l][k][768]
// CSR
__device__ __align__(128) int g_deg[N_NODES];
__device__ __align__(128) int g_rowptr[N_NODES + 1];
__device__ __align__(128) int g_wcnt[N_NODES];
__device__ __align__(128) int g_bsum[SCAN_B];
__device__ __align__(128) int g_boff[SCAN_B];
__device__ __align__(128) int g_csr[N_EDGES];     // (src<<3)|type

__device__ __forceinline__ void red_add_v4(float* addr, float4 v) {
    asm volatile("red.global.add.v4.f32 [%0], {%1,%2,%3,%4};"
                 :: "l"(addr), "f"(v.x), "f"(v.y), "f"(v.z), "f"(v.w) : "memory");
}

// ---------------- MMA helpers ----------------
__device__ __forceinline__ void ldsm4(uint32_t* r, uint32_t addr) {
    asm volatile("ldmatrix.sync.aligned.m8n8.x4.shared.b16 {%0,%1,%2,%3}, [%4];"
                 : "=r"(r[0]), "=r"(r[1]), "=r"(r[2]), "=r"(r[3]) : "r"(addr));
}
__device__ __forceinline__ void ldsm4t(uint32_t* r, uint32_t addr) {
    asm volatile("ldmatrix.sync.aligned.m8n8.x4.trans.shared.b16 {%0,%1,%2,%3}, [%4];"
                 : "=r"(r[0]), "=r"(r[1]), "=r"(r[2]), "=r"(r[3]) : "r"(addr));
}
__device__ __forceinline__ void mma16816(float* c, const uint32_t* a, const uint32_t* b) {
    asm volatile("mma.sync.aligned.m16n8k16.row.col.f32.f16.f16.f32 "
                 "{%0,%1,%2,%3}, {%4,%5,%6,%7}, {%8,%9}, {%0,%1,%2,%3};"
                 : "+f"(c[0]), "+f"(c[1]), "+f"(c[2]), "+f"(c[3])
                 : "r"(a[0]), "r"(a[1]), "r"(a[2]), "r"(a[3]), "r"(b[0]), "r"(b[1]));
}
__device__ __forceinline__ void cp16(uint32_t s, const void* g) {
    asm volatile("cp.async.cg.shared.global [%0], [%1], 16;" :: "r"(s), "l"(g));
}
__device__ __forceinline__ uint32_t smem_u32(const void* p) {
    return (uint32_t)__cvta_generic_to_shared(p);
}

// ---------------- precompute conversions ----------------
__global__ void convert_w_kernel(const float* __restrict__ Wq, const float* __restrict__ Wk,
                                 const float* __restrict__ Wv) {
    int idx = blockIdx.x * blockDim.x + threadIdx.x;
    if (idx >= NLAYER * DM * QKVW) return;
    int l = idx / (DM * QKVW);
    int r = idx - l * (DM * QKVW);
    int k = r / QKVW;
    int n = r - k * QKVW;
    int m = n >> 8;
    const float* W = (m == 0 ? Wq : (m == 1 ? Wk : Wv));
    g_wh[idx] = __float2half(W[l * DM * DM + k * DM + (n & 255)]);
}

__global__ void convert_x_kernel(const float* __restrict__ X) {
    int i4 = blockIdx.x * blockDim.x + threadIdx.x;
    if (i4 >= N_PAD * 64) return;
    int row = i4 >> 6;
    float4 f = make_float4(0.f, 0.f, 0.f, 0.f);
    if (row < N_NODES) f = ((const float4*)X)[i4];
    __half h[4];
    h[0] = __float2half(f.x); h[1] = __float2half(f.y);
    h[2] = __float2half(f.z); h[3] = __float2half(f.w);
    ((uint2*)g_xh)[i4] = *(uint2*)h;
}

// ---------------- CSR build ----------------
__global__ void zero_deg_kernel() {
    int i = blockIdx.x * blockDim.x + threadIdx.x;
    if (i < N_NODES) g_deg[i] = 0;
    if (i < NGRAPH * DM) g_pool[i] = 0.f;
    if (i < NGRAPH) g_cnt[i] = 0.f;
}
__global__ void hist_kernel(const int* __restrict__ dst) {
    int e = blockIdx.x * blockDim.x + threadIdx.x;
    if (e < N_EDGES) atomicAdd(&g_deg[dst[e]], 1);
}
// multi-block scan: per-block inclusive scan -> exclusive write + block sums
__global__ void scan1_kernel() {
    __shared__ int sh[1024];
    int t = threadIdx.x, b = blockIdx.x;
    int i = b * 1024 + t;
    int v = (i < N_NODES) ? g_deg[i] : 0;
    sh[t] = v;
    __syncthreads();
    for (int off = 1; off < 1024; off <<= 1) {
        int x = sh[t];
        if (t >= off) x += sh[t - off];
        __syncthreads();
        sh[t] = x;
        __syncthreads();
    }
    if (i < N_NODES) g_rowptr[i] = sh[t] - v;     // block-local exclusive
    if (t == 1023) g_bsum[b] = sh[1023];
}
__global__ void scan2_kernel() {      // 1 thread: 30 elems
    if (threadIdx.x == 0) {
        int run = 0;
        for (int b = 0; b < SCAN_B; b++) { g_boff[b] = run; run += g_bsum[b]; }
        g_rowptr[N_NODES] = run;
    }
}
__global__ void scan3_kernel() {
    int i = blockIdx.x * blockDim.x + threadIdx.x;
    if (i >= N_NODES) return;
    int v = g_rowptr[i] + g_boff[i >> 10];
    g_rowptr[i] = v;
    g_wcnt[i] = v;
}
__global__ void scatter_kernel(const int* __restrict__ src, const int* __restrict__ dst,
                               const int* __restrict__ et) {
    int e = blockIdx.x * blockDim.x + threadIdx.x;
    if (e >= N_EDGES) return;
    int p = atomicAdd(&g_wcnt[dst[e]], 1);
    g_csr[p] = (src[e] << 3) | et[e];
}

// ---------------- tensor-core QKV GEMM (fp16, 128x128 tile, 4-stage) ----------------
__global__ __launch_bounds__(256, 2) void gemm_qkv_mma(
    int layer,
    const float* __restrict__ bq, const float* __restrict__ bk, const float* __restrict__ bv)
{
    extern __shared__ __align__(16) __half smem[];

    const int t = threadIdx.x, lane = t & 31, wid = t >> 5;
    const int warp_m = wid >> 2, warp_n = wid & 3;
    const int bm = blockIdx.x, by = blockIdx.y;       // by in [0,6)
    const __half* Wh = g_wh + (size_t)layer * DM * QKVW;

    float acc[4][4][4];
#pragma unroll
    for (int i = 0; i < 4; i++)
#pragma unroll
        for (int j = 0; j < 4; j++)
#pragma unroll
            for (int c = 0; c < 4; c++) acc[i][j][c] = 0.f;

    const int a_row0 = t >> 2,         a_cg0 = t & 3;
    const int a_row1 = (t + 256) >> 2, a_cg1 = t & 3;
    const int b_row0 = t >> 4,         b_cg0 = t & 15;
    const int b_row1 = (t + 256) >> 4, b_cg1 = t & 15;

#define CP_CHUNK(kc, s) do {                                                          \
        int k0 = (kc) * 32;                                                           \
        __half* st = smem + (s) * STAGE_E;                                            \
        cp16(smem_u32(st + a_row0 * ASTRIDE + a_cg0 * 8),                             \
             g_xh + (size_t)(bm * 128 + a_row0) * 256 + k0 + a_cg0 * 8);              \
        cp16(smem_u32(st + a_row1 * ASTRIDE + a_cg1 * 8),                             \
             g_xh + (size_t)(bm * 128 + a_row1) * 256 + k0 + a_cg1 * 8);              \
        cp16(smem_u32(st + OFF_BH + b_row0 * BSTRIDE + b_cg0 * 8),                    \
             Wh + (size_t)(k0 + b_row0) * QKVW + by * 128 + b_cg0 * 8);               \
        cp16(smem_u32(st + OFF_BH + b_row1 * BSTRIDE + b_cg1 * 8),                    \
             Wh + (size_t)(k0 + b_row1) * QKVW + by * 128 + b_cg1 * 8);               \
        asm volatile("cp.async.commit_group;");                                       \
    } while (0)

    CP_CHUNK(0, 0);
    CP_CHUNK(1, 1);

    const int g = lane >> 3, ri = lane & 7;
    const uint32_t sb0 = smem_u32(smem);

    for (int kc = 0; kc < 8; kc++) {
        if (kc < 6) {
            CP_CHUNK(kc + 2, (kc + 2) & 3);
            asm volatile("cp.async.wait_group 2;" ::: "memory");
        } else if (kc == 6) {
            asm volatile("cp.async.wait_group 1;" ::: "memory");
        } else {
            asm volatile("cp.async.wait_group 0;" ::: "memory");
        }
        __syncthreads();

        const uint32_t base = sb0 + (uint32_t)((kc & 3) * STAGE_E * 2);

#pragma unroll
        for (int ks = 0; ks < 32; ks += 16) {
            uint32_t af[4][4];
#pragma unroll
            for (int mt = 0; mt < 4; mt++) {
                uint32_t eoff = (uint32_t)((warp_m * 64 + mt * 16 + (g & 1) * 8 + ri) * ASTRIDE
                                           + ks + (g >> 1) * 8) * 2u;
                ldsm4(af[mt], base + eoff);
            }
            uint32_t bfh[4][2];
#pragma unroll
            for (int ntp = 0; ntp < 2; ntp++) {
                uint32_t boff = (uint32_t)((ks + (g & 1) * 8 + ri) * BSTRIDE
                                           + warp_n * 32 + ntp * 16 + (g >> 1) * 8) * 2u;
                uint32_t r[4];
                ldsm4t(r, base + OFF_BH * 2 + boff);
                bfh[ntp * 2][0] = r[0]; bfh[ntp * 2][1] = r[1];
                bfh[ntp * 2 + 1][0] = r[2]; bfh[ntp * 2 + 1][1] = r[3];
            }
#pragma unroll
            for (int mt = 0; mt < 4; mt++)
#pragma unroll
                for (int nt = 0; nt < 4; nt++)
                    mma16816(acc[mt][nt], af[mt], bfh[nt]);
        }
    }

    const int sec = by >> 1;                          // 0=q, 1=k, 2=v
    const float* bias = sec == 0 ? bq : (sec == 1 ? bk : bv);
    const int lcol = (by & 1) * 128;
#pragma unroll
    for (int mt = 0; mt < 4; mt++)
#pragma unroll
        for (int nt = 0; nt < 4; nt++) {
            int r0 = bm * 128 + warp_m * 64 + mt * 16 + (lane >> 2);
            int ocol = warp_n * 32 + nt * 8 + (lane & 3) * 2;
            float b0 = bias[lcol + ocol], b1 = bias[lcol + ocol + 1];
            __half* dest0;
            __half* dest1;
            if (sec == 0) {
                dest0 = g_qh + (size_t)r0 * DM + lcol + ocol;
                dest1 = g_qh + (size_t)(r0 + 8) * DM + lcol + ocol;
            } else {
                size_t cbase = (size_t)(sec - 1) * 256 + lcol + ocol;
                dest0 = g_kv + (size_t)r0 * 512 + cbase;
                dest1 = g_kv + (size_t)(r0 + 8) * 512 + cbase;
            }
            if (r0 < N_NODES)
                *(__half2*)dest0 = __floats2half2_rn(acc[mt][nt][0] + b0, acc[mt][nt][1] + b1);
            if (r0 + 8 < N_NODES)
                *(__half2*)dest1 = __floats2half2_rn(acc[mt][nt][2] + b0, acc[mt][nt][3] + b1);
        }
#undef CP_CHUNK
}

// ---------------- fused attention: warp/dst, type-hoisted no-max softmax + ELU ----------
__global__ __launch_bounds__(256) void attn_kernel(const float* __restrict__ Ee,
                                                   const int* __restrict__ batch, int final_l)
{
    int d = (blockIdx.x * blockDim.x + threadIdx.x) >> 5;
    if (d >= N_NODES) return;
    int lane = threadIdx.x & 31;
    int myt = lane & 7;          // this lane owns type myt within its head group
    int grp = lane & 24;         // head-group base lane

    // q (fp16)
    float q[8];
    {
        uint4 qr = *(const uint4*)(g_qh + (size_t)d * DM + lane * 8);
        float2 f;
        f = __half22float2(*(__half2*)&qr.x);     q[0]=f.x; q[1]=f.y;
        f = __half22float2(((__half2*)&qr.x)[1]); q[2]=f.x; q[3]=f.y;
        f = __half22float2(*(__half2*)&qr.z);     q[4]=f.x; q[5]=f.y;
        f = __half22float2(((__half2*)&qr.z)[1]); q[6]=f.x; q[7]=f.y;
    }

    // precompute qe[t] = q . Ee[t] (head slice); lane grp+t holds type t
    float qe_reg = 0.f;
#pragma unroll
    for (int t = 0; t < 8; t++) {
        const float4* ep = (const float4*)(Ee + t * 256) + lane * 2;
        float4 ea = ep[0], eb = ep[1];
        float p = q[0]*ea.x + q[1]*ea.y + q[2]*ea.z + q[3]*ea.w
                + q[4]*eb.x + q[5]*eb.y + q[6]*eb.z + q[7]*eb.w;
        p += __shfl_xor_sync(0xffffffffu, p, 1, 8);
        p += __shfl_xor_sync(0xffffffffu, p, 2, 8);
        p += __shfl_xor_sync(0xffffffffu, p, 4, 8);
        if (t == myt) qe_reg = p;
    }

    int e0i = g_rowptr[d], e1i = g_rowptr[d + 1];
    float den = 0.f, ws = 0.f;
    float acc[8];
#pragma unroll
    for (int j = 0; j < 8; j++) acc[j] = 0.f;

    int e = e0i;
    for (; e + 2 <= e1i; e += 2) {
        int p0 = g_csr[e], p1 = g_csr[e + 1];
        int s0 = p0 >> 3, ty0 = p0 & 7;
        int s1 = p1 >> 3, ty1 = p1 & 7;
        uint4 k0r = *(const uint4*)(g_kv + (size_t)s0 * 512 + lane * 8);
        uint4 v0r = *(const uint4*)(g_kv + (size_t)s0 * 512 + 256 + lane * 8);
        uint4 k1r = *(const uint4*)(g_kv + (size_t)s1 * 512 + lane * 8);
        uint4 v1r = *(const uint4*)(g_kv + (size_t)s1 * 512 + 256 + lane * 8);

        float2 f;
        float d0, d1;
        {
            f = __half22float2(*(__half2*)&k0r.x);     d0  = q[0]*f.x + q[1]*f.y;
            f = __half22float2(((__half2*)&k0r.x)[1]); d0 += q[2]*f.x + q[3]*f.y;
            f = __half22float2(*(__half2*)&k0r.z);     d0 += q[4]*f.x + q[5]*f.y;
            f = __half22float2(((__half2*)&k0r.z)[1]); d0 += q[6]*f.x + q[7]*f.y;
            f = __half22float2(*(__half2*)&k1r.x);     d1  = q[0]*f.x + q[1]*f.y;
            f = __half22float2(((__half2*)&k1r.x)[1]); d1 += q[2]*f.x + q[3]*f.y;
            f = __half22float2(*(__half2*)&k1r.z);     d1 += q[4]*f.x + q[5]*f.y;
            f = __half22float2(((__half2*)&k1r.z)[1]); d1 += q[6]*f.x + q[7]*f.y;
        }
        d0 += __shfl_xor_sync(0xffffffffu, d0, 1, 8);
        d1 += __shfl_xor_sync(0xffffffffu, d1, 1, 8);
        d0 += __shfl_xor_sync(0xffffffffu, d0, 2, 8);
        d1 += __shfl_xor_sync(0xffffffffu, d1, 2, 8);
        d0 += __shfl_xor_sync(0xffffffffu, d0, 4, 8);
        d1 += __shfl_xor_sync(0xffffffffu, d1, 4, 8);
        float qe0 = __shfl_sync(0xffffffffu, qe_reg, grp + ty0);
        float qe1 = __shfl_sync(0xffffffffu, qe_reg, grp + ty1);
        float w0 = __expf((d0 + qe0) * 0.125f);
        float w1 = __expf((d1 + qe1) * 0.125f);
        den += w0 + w1;
        if (ty0 == myt) ws += w0;
        if (ty1 == myt) ws += w1;

        f = __half22float2(*(__half2*)&v0r.x);     acc[0]+=w0*f.x; acc[1]+=w0*f.y;
        f = __half22float2(((__half2*)&v0r.x)[1]); acc[2]+=w0*f.x; acc[3]+=w0*f.y;
        f = __half22float2(*(__half2*)&v0r.z);     acc[4]+=w0*f.x; acc[5]+=w0*f.y;
        f = __half22float2(((__half2*)&v0r.z)[1]); acc[6]+=w0*f.x; acc[7]+=w0*f.y;
        f = __half22float2(*(__half2*)&v1r.x);     acc[0]+=w1*f.x; acc[1]+=w1*f.y;
        f = __half22float2(((__half2*)&v1r.x)[1]); acc[2]+=w1*f.x; acc[3]+=w1*f.y;
        f = __half22float2(*(__half2*)&v1r.z);     acc[4]+=w1*f.x; acc[5]+=w1*f.y;
        f = __half22float2(((__half2*)&v1r.z)[1]); acc[6]+=w1*f.x; acc[7]+=w1*f.y;
    }
    if (e < e1i) {
        int p0 = g_csr[e];
        int s0 = p0 >> 3, ty0 = p0 & 7;
        uint4 k0r = *(const uint4*)(g_kv + (size_t)s0 * 512 + lane * 8);
        uint4 v0r = *(const uint4*)(g_kv + (size_t)s0 * 512 + 256 + lane * 8);
        float2 f;
        float d0;
        f = __half22float2(*(__half2*)&k0r.x);     d0  = q[0]*f.x + q[1]*f.y;
        f = __half22float2(((__half2*)&k0r.x)[1]); d0 += q[2]*f.x + q[3]*f.y;
        f = __half22float2(*(__half2*)&k0r.z);     d0 += q[4]*f.x + q[5]*f.y;
        f = __half22float2(((__half2*)&k0r.z)[1]); d0 += q[6]*f.x + q[7]*f.y;
        d0 += __shfl_xor_sync(0xffffffffu, d0, 1, 8);
        d0 += __shfl_xor_sync(0xffffffffu, d0, 2, 8);
        d0 += __shfl_xor_sync(0xffffffffu, d0, 4, 8);
        float qe0 = __shfl_sync(0xffffffffu, qe_reg, grp + ty0);
        float w0 = __expf((d0 + qe0) * 0.125f);
        den += w0;
        if (ty0 == myt) ws += w0;
        f = __half22float2(*(__half2*)&v0r.x);     acc[0]+=w0*f.x; acc[1]+=w0*f.y;
        f = __half22float2(((__half2*)&v0r.x)[1]); acc[2]+=w0*f.x; acc[3]+=w0*f.y;
        f = __half22float2(*(__half2*)&v0r.z);     acc[4]+=w0*f.x; acc[5]+=w0*f.y;
        f = __half22float2(((__half2*)&v0r.z)[1]); acc[6]+=w0*f.x; acc[7]+=w0*f.y;
    }

    // add edge-type contribution: acc += sum_t ws[t] * Ee[t]
#pragma unroll
    for (int t = 0; t < 8; t++) {
        float wt = __shfl_sync(0xffffffffu, ws, grp + t);
        const float4* ep = (const float4*)(Ee + t * 256) + lane * 2;
        float4 ea = ep[0], eb = ep[1];
        acc[0] += wt * ea.x; acc[1] += wt * ea.y; acc[2] += wt * ea.z; acc[3] += wt * ea.w;
        acc[4] += wt * eb.x; acc[5] += wt * eb.y; acc[6] += wt * eb.z; acc[7] += wt * eb.w;
    }

    float inv = den > 0.f ? 1.f / (den + 1e-16f) : 0.f;
    float o[8];
#pragma unroll
    for (int j = 0; j < 8; j++) {
        float v = acc[j] * inv;
        o[j] = v > 0.f ? v : expm1f(v);
    }
    if (final_l) {
        int b = batch[d];
        float* p = g_pool + (size_t)b * DM + lane * 8;
        red_add_v4(p,     make_float4(o[0], o[1], o[2], o[3]));
        red_add_v4(p + 4, make_float4(o[4], o[5], o[6], o[7]));
        if (lane == 0) atomicAdd(&g_cnt[b], 1.0f);
    } else {
        __half h[8];
#pragma unroll
        for (int j = 0; j < 8; j++) h[j] = __float2half(o[j]);
        *(uint4*)(g_xh + (size_t)d * DM + lane * 8) = *(uint4*)h;
    }
}

// ---------------- GRU + FC ----------------
__global__ void gru_fc(const float* __restrict__ W_ih, const float* __restrict__ b_ih,
                       const float* __restrict__ b_hh,
                       const float* __restrict__ W_fc, const float* __restrict__ b_fc,
                       float* __restrict__ out)
{
    __shared__ float gsh[256];
    __shared__ float gish[192];
    __shared__ float hsh[64];
    int b = blockIdx.x;
    int t = threadIdx.x;
    float inv = 1.0f / fmaxf(g_cnt[b], 1.0f);
    gsh[t] = g_pool[b * DM + t] * inv;
    __syncthreads();
    if (t < 192) {
        float s = b_ih[t];
        const float* w = W_ih + t * 256;
#pragma unroll 8
        for (int k = 0; k < 256; k++) s += gsh[k] * w[k];
        gish[t] = s;
    }
    __syncthreads();
    if (t < 64) {
        float r = 1.f / (1.f + expf(-(gish[t] + b_hh[t])));
        float z = 1.f / (1.f + expf(-(gish[64 + t] + b_hh[64 + t])));
        float n = tanhf(gish[128 + t] + r * b_hh[128 + t]);
        hsh[t] = (1.f - z) * n;
    }
    __syncthreads();
    if (t < 2) {
        float s = b_fc[t];
        const float* w = W_fc + t * 64;
#pragma unroll
        for (int k = 0; k < 64; k++) s += hsh[k] * w[k];
        out[b * 2 + t] = s;
    }
}

// ---------------- launch ----------------
extern "C" void kernel_launch(void* const* d_in, const int* in_sizes, int n_in,
                              void* d_out, int out_size)
{
    const float* x     = (const float*)d_in[0];
    const int*   eidx  = (const int*)d_in[1];
    const int*   batch = (const int*)d_in[2];
    const int*   etid  = (const int*)d_in[3];
    const float* Wq    = (const float*)d_in[4];
    const float* bq    = (const float*)d_in[5];
    const float* Wk    = (const float*)d_in[6];
    const float* bk    = (const float*)d_in[7];
    const float* Wv    = (const float*)d_in[8];
    const float* bv    = (const float*)d_in[9];
    const float* Ee    = (const float*)d_in[10];
    const float* W_ih  = (const float*)d_in[11];
    const float* b_ih  = (const float*)d_in[12];
    const float* b_hh  = (const float*)d_in[14];
    const float* W_fc  = (const float*)d_in[15];
    const float* b_fc  = (const float*)d_in[16];

    const int* src = eidx;
    const int* dst = eidx + N_EDGES;

    static int smem_set = 0;
    const int gemm_smem = 4 * STAGE_E * (int)sizeof(__half);   // 75776 B
    if (!smem_set) {
        cudaFuncSetAttribute(gemm_qkv_mma, cudaFuncAttributeMaxDynamicSharedMemorySize, gemm_smem);
        smem_set = 1;
    }

    convert_w_kernel<<<(NLAYER * DM * QKVW + 255) / 256, 256>>>(Wq, Wk, Wv);
    convert_x_kernel<<<(N_PAD * 64 + 255) / 256, 256>>>(x);

    zero_deg_kernel<<<(N_NODES + 255) / 256, 256>>>();   // also zeroes pool/cnt
    hist_kernel<<<(N_EDGES + 255) / 256, 256>>>(dst);
    scan1_kernel<<<SCAN_B, 1024>>>();
    scan2_kernel<<<1, 32>>>();
    scan3_kernel<<<(N_NODES + 255) / 256, 256>>>();
    scatter_kernel<<<(N_EDGES + 255) / 256, 256>>>(src, dst, etid);

    dim3 ggrid(N_PAD / 128, 6);
    for (int l = 0; l < NLAYER; l++) {
        gemm_qkv_mma<<<ggrid, 256, gemm_smem>>>(l, bq + l * DM, bk + l * DM, bv + l * DM);
        attn_kernel<<<(N_NODES * 32 + 255) / 256, 256>>>(Ee + l * 8 * DM, batch,
                                                         l == NLAYER - 1 ? 1 : 0);
    }
    gru_fc<<<NGRAPH, 256>>>(W_ih, b_ih, b_hh, W_fc, b_fc, (float*)d_out);
}

// round 13
// speedup vs baseline: 1.8148x; 1.8148x over previous
#include <cuda_runtime.h>
#include <cuda_fp16.h>
#include <cstdint>

#define N_NODES 30000
#define N_PAD   30080           // 235 * 128
#define N_EDGES 240000
#define DM 256
#define QKVW 768
#define NGRAPH 64
#define NLAYER 3
#define SCAN_B  30              // ceil(30000/1024)

// GEMM smem layout (fp16 elems per stage): Ah 128x40, Bh 32x136
#define ASTRIDE 40
#define BSTRIDE 136
#define OFF_BH  5120
#define STAGE_E 9472            // elems per stage (18944 B); 4 stages = 75776 B

// ---------------- scratch ----------------
__device__ __align__(128) float  g_q[N_NODES * DM];        // fp32 q
__device__ __align__(128) __half g_kv[N_NODES * 512];      // fp16 k | v
__device__ __align__(128) float  g_pool[NGRAPH * DM];
__device__ __align__(128) float  g_cnt[NGRAPH];
__device__ __align__(128) __half g_xh[N_PAD * DM];         // fp16 activations (row-major)
__device__ __align__(128) __half g_wh[NLAYER * DM * QKVW]; // fp16 W, [l][k][768]
// CSR
__device__ __align__(128) int g_deg[N_NODES];
__device__ __align__(128) int g_rowptr[N_NODES + 1];
__device__ __align__(128) int g_wcnt[N_NODES];
__device__ __align__(128) int g_bsum[SCAN_B];
__device__ __align__(128) int g_boff[SCAN_B];
__device__ __align__(128) int g_csr[N_EDGES];     // (src<<3)|type

__device__ __forceinline__ void red_add_v4(float* addr, float4 v) {
    asm volatile("red.global.add.v4.f32 [%0], {%1,%2,%3,%4};"
                 :: "l"(addr), "f"(v.x), "f"(v.y), "f"(v.z), "f"(v.w) : "memory");
}

// ---------------- MMA helpers ----------------
__device__ __forceinline__ void ldsm4(uint32_t* r, uint32_t addr) {
    asm volatile("ldmatrix.sync.aligned.m8n8.x4.shared.b16 {%0,%1,%2,%3}, [%4];"
                 : "=r"(r[0]), "=r"(r[1]), "=r"(r[2]), "=r"(r[3]) : "r"(addr));
}
__device__ __forceinline__ void ldsm4t(uint32_t* r, uint32_t addr) {
    asm volatile("ldmatrix.sync.aligned.m8n8.x4.trans.shared.b16 {%0,%1,%2,%3}, [%4];"
                 : "=r"(r[0]), "=r"(r[1]), "=r"(r[2]), "=r"(r[3]) : "r"(addr));
}
__device__ __forceinline__ void mma16816(float* c, const uint32_t* a, const uint32_t* b) {
    asm volatile("mma.sync.aligned.m16n8k16.row.col.f32.f16.f16.f32 "
                 "{%0,%1,%2,%3}, {%4,%5,%6,%7}, {%8,%9}, {%0,%1,%2,%3};"
                 : "+f"(c[0]), "+f"(c[1]), "+f"(c[2]), "+f"(c[3])
                 : "r"(a[0]), "r"(a[1]), "r"(a[2]), "r"(a[3]), "r"(b[0]), "r"(b[1]));
}
__device__ __forceinline__ void cp16(uint32_t s, const void* g) {
    asm volatile("cp.async.cg.shared.global [%0], [%1], 16;" :: "r"(s), "l"(g));
}
__device__ __forceinline__ uint32_t smem_u32(const void* p) {
    return (uint32_t)__cvta_generic_to_shared(p);
}

// ---------------- precompute conversions ----------------
__global__ void convert_w_kernel(const float* __restrict__ Wq, const float* __restrict__ Wk,
                                 const float* __restrict__ Wv) {
    int idx = blockIdx.x * blockDim.x + threadIdx.x;
    if (idx >= NLAYER * DM * QKVW) return;
    int l = idx / (DM * QKVW);
    int r = idx - l * (DM * QKVW);
    int k = r / QKVW;
    int n = r - k * QKVW;
    int m = n >> 8;
    const float* W = (m == 0 ? Wq : (m == 1 ? Wk : Wv));
    g_wh[idx] = __float2half(W[l * DM * DM + k * DM + (n & 255)]);
}

// also zeroes deg/pool/cnt (prologue fusion; all precede hist/attn)
__global__ void convert_x_kernel(const float* __restrict__ X) {
    int i4 = blockIdx.x * blockDim.x + threadIdx.x;
    if (i4 < N_NODES) g_deg[i4] = 0;
    if (i4 < NGRAPH * DM) g_pool[i4] = 0.f;
    if (i4 < NGRAPH) g_cnt[i4] = 0.f;
    if (i4 >= N_PAD * 64) return;
    int row = i4 >> 6;
    float4 f = make_float4(0.f, 0.f, 0.f, 0.f);
    if (row < N_NODES) f = ((const float4*)X)[i4];
    __half h[4];
    h[0] = __float2half(f.x); h[1] = __float2half(f.y);
    h[2] = __float2half(f.z); h[3] = __float2half(f.w);
    ((uint2*)g_xh)[i4] = *(uint2*)h;
}

// ---------------- CSR build ----------------
__global__ void hist_kernel(const int* __restrict__ dst) {
    int e = blockIdx.x * blockDim.x + threadIdx.x;
    if (e < N_EDGES) atomicAdd(&g_deg[dst[e]], 1);
}
// multi-block scan: per-block inclusive scan -> exclusive write + block sums
__global__ void scan1_kernel() {
    __shared__ int sh[1024];
    int t = threadIdx.x, b = blockIdx.x;
    int i = b * 1024 + t;
    int v = (i < N_NODES) ? g_deg[i] : 0;
    sh[t] = v;
    __syncthreads();
    for (int off = 1; off < 1024; off <<= 1) {
        int x = sh[t];
        if (t >= off) x += sh[t - off];
        __syncthreads();
        sh[t] = x;
        __syncthreads();
    }
    if (i < N_NODES) g_rowptr[i] = sh[t] - v;     // block-local exclusive
    if (t == 1023) g_bsum[b] = sh[1023];
}
__global__ void scan2_kernel() {      // 1 thread: 30 elems
    if (threadIdx.x == 0) {
        int run = 0;
        for (int b = 0; b < SCAN_B; b++) { g_boff[b] = run; run += g_bsum[b]; }
        g_rowptr[N_NODES] = run;
    }
}
__global__ void scan3_kernel() {
    int i = blockIdx.x * blockDim.x + threadIdx.x;
    if (i >= N_NODES) return;
    int v = g_rowptr[i] + g_boff[i >> 10];
    g_rowptr[i] = v;
    g_wcnt[i] = v;
}
__global__ void scatter_kernel(const int* __restrict__ src, const int* __restrict__ dst,
                               const int* __restrict__ et) {
    int e = blockIdx.x * blockDim.x + threadIdx.x;
    if (e >= N_EDGES) return;
    int p = atomicAdd(&g_wcnt[dst[e]], 1);
    g_csr[p] = (src[e] << 3) | et[e];
}

// ---------------- tensor-core QKV GEMM (fp16, 128x128 tile, 4-stage) ----------------
__global__ __launch_bounds__(256, 2) void gemm_qkv_mma(
    int layer,
    const float* __restrict__ bq, const float* __restrict__ bk, const float* __restrict__ bv)
{
    extern __shared__ __align__(16) __half smem[];

    const int t = threadIdx.x, lane = t & 31, wid = t >> 5;
    const int warp_m = wid >> 2, warp_n = wid & 3;
    const int bm = blockIdx.x, by = blockIdx.y;       // by in [0,6)
    const __half* Wh = g_wh + (size_t)layer * DM * QKVW;

    float acc[4][4][4];
#pragma unroll
    for (int i = 0; i < 4; i++)
#pragma unroll
        for (int j = 0; j < 4; j++)
#pragma unroll
            for (int c = 0; c < 4; c++) acc[i][j][c] = 0.f;

    const int a_row0 = t >> 2,         a_cg0 = t & 3;
    const int a_row1 = (t + 256) >> 2, a_cg1 = t & 3;
    const int b_row0 = t >> 4,         b_cg0 = t & 15;
    const int b_row1 = (t + 256) >> 4, b_cg1 = t & 15;

#define CP_CHUNK(kc, s) do {                                                          \
        int k0 = (kc) * 32;                                                           \
        __half* st = smem + (s) * STAGE_E;                                            \
        cp16(smem_u32(st + a_row0 * ASTRIDE + a_cg0 * 8),                             \
             g_xh + (size_t)(bm * 128 + a_row0) * 256 + k0 + a_cg0 * 8);              \
        cp16(smem_u32(st + a_row1 * ASTRIDE + a_cg1 * 8),                             \
             g_xh + (size_t)(bm * 128 + a_row1) * 256 + k0 + a_cg1 * 8);              \
        cp16(smem_u32(st + OFF_BH + b_row0 * BSTRIDE + b_cg0 * 8),                    \
             Wh + (size_t)(k0 + b_row0) * QKVW + by * 128 + b_cg0 * 8);               \
        cp16(smem_u32(st + OFF_BH + b_row1 * BSTRIDE + b_cg1 * 8),                    \
             Wh + (size_t)(k0 + b_row1) * QKVW + by * 128 + b_cg1 * 8);               \
        asm volatile("cp.async.commit_group;");                                       \
    } while (0)

    CP_CHUNK(0, 0);
    CP_CHUNK(1, 1);

    const int g = lane >> 3, ri = lane & 7;
    const uint32_t sb0 = smem_u32(smem);

    for (int kc = 0; kc < 8; kc++) {
        if (kc < 6) {
            CP_CHUNK(kc + 2, (kc + 2) & 3);
            asm volatile("cp.async.wait_group 2;" ::: "memory");
        } else if (kc == 6) {
            asm volatile("cp.async.wait_group 1;" ::: "memory");
        } else {
            asm volatile("cp.async.wait_group 0;" ::: "memory");
        }
        __syncthreads();

        const uint32_t base = sb0 + (uint32_t)((kc & 3) * STAGE_E * 2);

#pragma unroll
        for (int ks = 0; ks < 32; ks += 16) {
            uint32_t af[4][4];
#pragma unroll
            for (int mt = 0; mt < 4; mt++) {
                uint32_t eoff = (uint32_t)((warp_m * 64 + mt * 16 + (g & 1) * 8 + ri) * ASTRIDE
                                           + ks + (g >> 1) * 8) * 2u;
                ldsm4(af[mt], base + eoff);
            }
            uint32_t bfh[4][2];
#pragma unroll
            for (int ntp = 0; ntp < 2; ntp++) {
                uint32_t boff = (uint32_t)((ks + (g & 1) * 8 + ri) * BSTRIDE
                                           + warp_n * 32 + ntp * 16 + (g >> 1) * 8) * 2u;
                uint32_t r[4];
                ldsm4t(r, base + OFF_BH * 2 + boff);
                bfh[ntp * 2][0] = r[0]; bfh[ntp * 2][1] = r[1];
                bfh[ntp * 2 + 1][0] = r[2]; bfh[ntp * 2 + 1][1] = r[3];
            }
#pragma unroll
            for (int mt = 0; mt < 4; mt++)
#pragma unroll
                for (int nt = 0; nt < 4; nt++)
                    mma16816(acc[mt][nt], af[mt], bfh[nt]);
        }
    }

    const int sec = by >> 1;                          // 0=q, 1=k, 2=v
    const float* bias = sec == 0 ? bq : (sec == 1 ? bk : bv);
    const int lcol = (by & 1) * 128;
#pragma unroll
    for (int mt = 0; mt < 4; mt++)
#pragma unroll
        for (int nt = 0; nt < 4; nt++) {
            int r0 = bm * 128 + warp_m * 64 + mt * 16 + (lane >> 2);
            int ocol = warp_n * 32 + nt * 8 + (lane & 3) * 2;
            float b0 = bias[lcol + ocol], b1 = bias[lcol + ocol + 1];
            if (sec == 0) {
                if (r0 < N_NODES)
                    *(float2*)(g_q + (size_t)r0 * DM + lcol + ocol) =
                        make_float2(acc[mt][nt][0] + b0, acc[mt][nt][1] + b1);
                if (r0 + 8 < N_NODES)
                    *(float2*)(g_q + (size_t)(r0 + 8) * DM + lcol + ocol) =
                        make_float2(acc[mt][nt][2] + b0, acc[mt][nt][3] + b1);
            } else {
                size_t cbase = (size_t)(sec - 1) * 256 + lcol + ocol;
                if (r0 < N_NODES)
                    *(__half2*)(g_kv + (size_t)r0 * 512 + cbase) =
                        __floats2half2_rn(acc[mt][nt][0] + b0, acc[mt][nt][1] + b1);
                if (r0 + 8 < N_NODES)
                    *(__half2*)(g_kv + (size_t)(r0 + 8) * 512 + cbase) =
                        __floats2half2_rn(acc[mt][nt][2] + b0, acc[mt][nt][3] + b1);
            }
        }
#undef CP_CHUNK
}

// ---------------- fused attention: warp/dst, online softmax + ELU; 2x unrolled ----------
__global__ __launch_bounds__(256) void attn_kernel(const float* __restrict__ Ee,
                                                   const int* __restrict__ batch, int final_l)
{
    int d = (blockIdx.x * blockDim.x + threadIdx.x) >> 5;
    if (d >= N_NODES) return;
    int lane = threadIdx.x & 31;

    const float4* qp = (const float4*)(g_q + (size_t)d * DM) + lane * 2;
    float4 q0 = qp[0], q1 = qp[1];

    int e0i = g_rowptr[d], e1i = g_rowptr[d + 1];
    float m = -1e30f, den = 0.f;
    float acc[8];
#pragma unroll
    for (int j = 0; j < 8; j++) acc[j] = 0.f;

    int e = e0i;
    for (; e + 2 <= e1i; e += 2) {
        int p0 = g_csr[e], p1 = g_csr[e + 1];
        int s0 = p0 >> 3, ty0 = p0 & 7;
        int s1 = p1 >> 3, ty1 = p1 & 7;
        uint4 k0r = *(const uint4*)(g_kv + (size_t)s0 * 512 + lane * 8);
        uint4 v0r = *(const uint4*)(g_kv + (size_t)s0 * 512 + 256 + lane * 8);
        uint4 k1r = *(const uint4*)(g_kv + (size_t)s1 * 512 + lane * 8);
        uint4 v1r = *(const uint4*)(g_kv + (size_t)s1 * 512 + 256 + lane * 8);
        const float4* e0p = (const float4*)(Ee + ty0 * 256) + lane * 2;
        const float4* e1p = (const float4*)(Ee + ty1 * 256) + lane * 2;
        float4 ea0 = e0p[0], ea1 = e0p[1];
        float4 eb0 = e1p[0], eb1 = e1p[1];

        float ke0[8], ve0[8], ke1[8], ve1[8];
        {
            float2 kf[4], vf[4];
            kf[0] = __half22float2(*(__half2*)&k0r.x); kf[1] = __half22float2(*(__half2*)&k0r.y);
            kf[2] = __half22float2(*(__half2*)&k0r.z); kf[3] = __half22float2(*(__half2*)&k0r.w);
            vf[0] = __half22float2(*(__half2*)&v0r.x); vf[1] = __half22float2(*(__half2*)&v0r.y);
            vf[2] = __half22float2(*(__half2*)&v0r.z); vf[3] = __half22float2(*(__half2*)&v0r.w);
            ke0[0]=kf[0].x+ea0.x; ke0[1]=kf[0].y+ea0.y; ke0[2]=kf[1].x+ea0.z; ke0[3]=kf[1].y+ea0.w;
            ke0[4]=kf[2].x+ea1.x; ke0[5]=kf[2].y+ea1.y; ke0[6]=kf[3].x+ea1.z; ke0[7]=kf[3].y+ea1.w;
            ve0[0]=vf[0].x+ea0.x; ve0[1]=vf[0].y+ea0.y; ve0[2]=vf[1].x+ea0.z; ve0[3]=vf[1].y+ea0.w;
            ve0[4]=vf[2].x+ea1.x; ve0[5]=vf[2].y+ea1.y; ve0[6]=vf[3].x+ea1.z; ve0[7]=vf[3].y+ea1.w;
        }
        {
            float2 kf[4], vf[4];
            kf[0] = __half22float2(*(__half2*)&k1r.x); kf[1] = __half22float2(*(__half2*)&k1r.y);
            kf[2] = __half22float2(*(__half2*)&k1r.z); kf[3] = __half22float2(*(__half2*)&k1r.w);
            vf[0] = __half22float2(*(__half2*)&v1r.x); vf[1] = __half22float2(*(__half2*)&v1r.y);
            vf[2] = __half22float2(*(__half2*)&v1r.z); vf[3] = __half22float2(*(__half2*)&v1r.w);
            ke1[0]=kf[0].x+eb0.x; ke1[1]=kf[0].y+eb0.y; ke1[2]=kf[1].x+eb0.z; ke1[3]=kf[1].y+eb0.w;
            ke1[4]=kf[2].x+eb1.x; ke1[5]=kf[2].y+eb1.y; ke1[6]=kf[3].x+eb1.z; ke1[7]=kf[3].y+eb1.w;
            ve1[0]=vf[0].x+eb0.x; ve1[1]=vf[0].y+eb0.y; ve1[2]=vf[1].x+eb0.z; ve1[3]=vf[1].y+eb0.w;
            ve1[4]=vf[2].x+eb1.x; ve1[5]=vf[2].y+eb1.y; ve1[6]=vf[3].x+eb1.z; ve1[7]=vf[3].y+eb1.w;
        }

        float pa = q0.x*ke0[0]+q0.y*ke0[1]+q0.z*ke0[2]+q0.w*ke0[3]
                 + q1.x*ke0[4]+q1.y*ke0[5]+q1.z*ke0[6]+q1.w*ke0[7];
        float pb = q0.x*ke1[0]+q0.y*ke1[1]+q0.z*ke1[2]+q0.w*ke1[3]
                 + q1.x*ke1[4]+q1.y*ke1[5]+q1.z*ke1[6]+q1.w*ke1[7];
        pa += __shfl_xor_sync(0xffffffffu, pa, 1, 8);
        pb += __shfl_xor_sync(0xffffffffu, pb, 1, 8);
        pa += __shfl_xor_sync(0xffffffffu, pa, 2, 8);
        pb += __shfl_xor_sync(0xffffffffu, pb, 2, 8);
        pa += __shfl_xor_sync(0xffffffffu, pa, 4, 8);
        pb += __shfl_xor_sync(0xffffffffu, pb, 4, 8);
        float sc0 = pa * 0.125f, sc1 = pb * 0.125f;

        float mn = fmaxf(m, sc0);
        float scale = __expf(m - mn);
        float w = __expf(sc0 - mn);
        den = den * scale + w;
#pragma unroll
        for (int j = 0; j < 8; j++) acc[j] = acc[j] * scale + w * ve0[j];
        m = mn;

        mn = fmaxf(m, sc1);
        scale = __expf(m - mn);
        w = __expf(sc1 - mn);
        den = den * scale + w;
#pragma unroll
        for (int j = 0; j < 8; j++) acc[j] = acc[j] * scale + w * ve1[j];
        m = mn;
    }
    if (e < e1i) {
        int p0 = g_csr[e];
        int s0 = p0 >> 3, ty0 = p0 & 7;
        uint4 k0r = *(const uint4*)(g_kv + (size_t)s0 * 512 + lane * 8);
        uint4 v0r = *(const uint4*)(g_kv + (size_t)s0 * 512 + 256 + lane * 8);
        const float4* e0p = (const float4*)(Ee + ty0 * 256) + lane * 2;
        float4 ea0 = e0p[0], ea1 = e0p[1];
        float2 kf[4], vf[4];
        kf[0] = __half22float2(*(__half2*)&k0r.x); kf[1] = __half22float2(*(__half2*)&k0r.y);
        kf[2] = __half22float2(*(__half2*)&k0r.z); kf[3] = __half22float2(*(__half2*)&k0r.w);
        vf[0] = __half22float2(*(__half2*)&v0r.x); vf[1] = __half22float2(*(__half2*)&v0r.y);
        vf[2] = __half22float2(*(__half2*)&v0r.z); vf[3] = __half22float2(*(__half2*)&v0r.w);
        float ke0[8], ve0[8];
        ke0[0]=kf[0].x+ea0.x; ke0[1]=kf[0].y+ea0.y; ke0[2]=kf[1].x+ea0.z; ke0[3]=kf[1].y+ea0.w;
        ke0[4]=kf[2].x+ea1.x; ke0[5]=kf[2].y+ea1.y; ke0[6]=kf[3].x+ea1.z; ke0[7]=kf[3].y+ea1.w;
        ve0[0]=vf[0].x+ea0.x; ve0[1]=vf[0].y+ea0.y; ve0[2]=vf[1].x+ea0.z; ve0[3]=vf[1].y+ea0.w;
        ve0[4]=vf[2].x+ea1.x; ve0[5]=vf[2].y+ea1.y; ve0[6]=vf[3].x+ea1.z; ve0[7]=vf[3].y+ea1.w;
        float pa = q0.x*ke0[0]+q0.y*ke0[1]+q0.z*ke0[2]+q0.w*ke0[3]
                 + q1.x*ke0[4]+q1.y*ke0[5]+q1.z*ke0[6]+q1.w*ke0[7];
        pa += __shfl_xor_sync(0xffffffffu, pa, 1, 8);
        pa += __shfl_xor_sync(0xffffffffu, pa, 2, 8);
        pa += __shfl_xor_sync(0xffffffffu, pa, 4, 8);
        float sc0 = pa * 0.125f;
        float mn = fmaxf(m, sc0);
        float scale = __expf(m - mn);
        float w = __expf(sc0 - mn);
        den = den * scale + w;
#pragma unroll
        for (int j = 0; j < 8; j++) acc[j] = acc[j] * scale + w * ve0[j];
        m = mn;
    }

    float inv = den > 0.f ? 1.f / den : 0.f;
    float o[8];
#pragma unroll
    for (int j = 0; j < 8; j++) {
        float v = acc[j] * inv;
        o[j] = v > 0.f ? v : expm1f(v);
    }
    if (final_l) {
        int b = batch[d];
        float* p = g_pool + (size_t)b * DM + lane * 8;
        red_add_v4(p,     make_float4(o[0], o[1], o[2], o[3]));
        red_add_v4(p + 4, make_float4(o[4], o[5], o[6], o[7]));
        if (lane == 0) atomicAdd(&g_cnt[b], 1.0f);
    } else {
        __half h[8];
#pragma unroll
        for (int j = 0; j < 8; j++) h[j] = __float2half(o[j]);
        *(uint4*)(g_xh + (size_t)d * DM + lane * 8) = *(uint4*)h;
    }
}

// ---------------- GRU + FC ----------------
__global__ void gru_fc(const float* __restrict__ W_ih, const float* __restrict__ b_ih,
                       const float* __restrict__ b_hh,
                       const float* __restrict__ W_fc, const float* __restrict__ b_fc,
                       float* __restrict__ out)
{
    __shared__ float gsh[256];
    __shared__ float gish[192];
    __shared__ float hsh[64];
    int b = blockIdx.x;
    int t = threadIdx.x;
    float inv = 1.0f / fmaxf(g_cnt[b], 1.0f);
    gsh[t] = g_pool[b * DM + t] * inv;
    __syncthreads();
    if (t < 192) {
        float s = b_ih[t];
        const float* w = W_ih + t * 256;
#pragma unroll 8
        for (int k = 0; k < 256; k++) s += gsh[k] * w[k];
        gish[t] = s;
    }
    __syncthreads();
    if (t < 64) {
        float r = 1.f / (1.f + expf(-(gish[t] + b_hh[t])));
        float z = 1.f / (1.f + expf(-(gish[64 + t] + b_hh[64 + t])));
        float n = tanhf(gish[128 + t] + r * b_hh[128 + t]);
        hsh[t] = (1.f - z) * n;
    }
    __syncthreads();
    if (t < 2) {
        float s = b_fc[t];
        const float* w = W_fc + t * 64;
#pragma unroll
        for (int k = 0; k < 64; k++) s += hsh[k] * w[k];
        out[b * 2 + t] = s;
    }
}

// ---------------- launch ----------------
extern "C" void kernel_launch(void* const* d_in, const int* in_sizes, int n_in,
                              void* d_out, int out_size)
{
    const float* x     = (const float*)d_in[0];
    const int*   eidx  = (const int*)d_in[1];
    const int*   batch = (const int*)d_in[2];
    const int*   etid  = (const int*)d_in[3];
    const float* Wq    = (const float*)d_in[4];
    const float* bq    = (const float*)d_in[5];
    const float* Wk    = (const float*)d_in[6];
    const float* bk    = (const float*)d_in[7];
    const float* Wv    = (const float*)d_in[8];
    const float* bv    = (const float*)d_in[9];
    const float* Ee    = (const float*)d_in[10];
    const float* W_ih  = (const float*)d_in[11];
    const float* b_ih  = (const float*)d_in[12];
    const float* b_hh  = (const float*)d_in[14];
    const float* W_fc  = (const float*)d_in[15];
    const float* b_fc  = (const float*)d_in[16];

    const int* src = eidx;
    const int* dst = eidx + N_EDGES;

    static int smem_set = 0;
    const int gemm_smem = 4 * STAGE_E * (int)sizeof(__half);   // 75776 B
    if (!smem_set) {
        cudaFuncSetAttribute(gemm_qkv_mma, cudaFuncAttributeMaxDynamicSharedMemorySize, gemm_smem);
        smem_set = 1;
    }

    convert_w_kernel<<<(NLAYER * DM * QKVW + 255) / 256, 256>>>(Wq, Wk, Wv);
    convert_x_kernel<<<(N_PAD * 64 + 255) / 256, 256>>>(x);   // also zeroes deg/pool/cnt

    hist_kernel<<<(N_EDGES + 255) / 256, 256>>>(dst);
    scan1_kernel<<<SCAN_B, 1024>>>();
    scan2_kernel<<<1, 32>>>();
    scan3_kernel<<<(N_NODES + 255) / 256, 256>>>();
    scatter_kernel<<<(N_EDGES + 255) / 256, 256>>>(src, dst, etid);

    dim3 ggrid(N_PAD / 128, 6);
    for (int l = 0; l < NLAYER; l++) {
        gemm_qkv_mma<<<ggrid, 256, gemm_smem>>>(l, bq + l * DM, bk + l * DM, bv + l * DM);
        attn_kernel<<<(N_NODES * 32 + 255) / 256, 256>>>(Ee + l * 8 * DM, batch,
                                                         l == NLAYER - 1 ? 1 : 0);
    }
    gru_fc<<<NGRAPH, 256>>>(W_ih, b_ih, b_hh, W_fc, b_fc, (float*)d_out);
}

// round 14
// speedup vs baseline: 1.8166x; 1.0010x over previous
#include <cuda_runtime.h>
#include <cuda_fp16.h>
#include <cstdint>

#define N_NODES 30000
#define N_PAD   30080           // 235 * 128
#define N_EDGES 240000
#define DM 256
#define QKVW 768
#define NGRAPH 64
#define NLAYER 3
#define SCAN_B  30              // ceil(30000/1024)

// GEMM smem layout (fp16 elems per stage): Ah 128x40, Bh 32x136
#define ASTRIDE 40
#define BSTRIDE 136
#define OFF_BH  5120
#define STAGE_E 9472            // elems per stage (18944 B); 4 stages = 75776 B

// ---------------- scratch ----------------
__device__ __align__(128) float  g_q[N_NODES * DM];        // fp32 q
__device__ __align__(128) __half g_kv[N_NODES * 512];      // fp16 k | v
__device__ __align__(128) float  g_pool[NGRAPH * DM];
__device__ __align__(128) float  g_cnt[NGRAPH];
__device__ __align__(128) __half g_xh[N_PAD * DM];         // fp16 activations (row-major)
__device__ __align__(128) __half g_wh[NLAYER * DM * QKVW]; // fp16 W, [l][k][768]
// CSR
__device__ __align__(128) int g_deg[N_NODES];
__device__ __align__(128) int g_rowptr[N_NODES + 1];
__device__ __align__(128) int g_wcnt[N_NODES];
__device__ __align__(128) int g_bsum[SCAN_B];
__device__ __align__(128) int g_boff[SCAN_B];
__device__ __align__(128) int g_csr[N_EDGES];     // (src<<3)|type

__device__ __forceinline__ void red_add_v4(float* addr, float4 v) {
    asm volatile("red.global.add.v4.f32 [%0], {%1,%2,%3,%4};"
                 :: "l"(addr), "f"(v.x), "f"(v.y), "f"(v.z), "f"(v.w) : "memory");
}

// ---------------- MMA helpers ----------------
__device__ __forceinline__ void ldsm4(uint32_t* r, uint32_t addr) {
    asm volatile("ldmatrix.sync.aligned.m8n8.x4.shared.b16 {%0,%1,%2,%3}, [%4];"
                 : "=r"(r[0]), "=r"(r[1]), "=r"(r[2]), "=r"(r[3]) : "r"(addr));
}
__device__ __forceinline__ void ldsm4t(uint32_t* r, uint32_t addr) {
    asm volatile("ldmatrix.sync.aligned.m8n8.x4.trans.shared.b16 {%0,%1,%2,%3}, [%4];"
                 : "=r"(r[0]), "=r"(r[1]), "=r"(r[2]), "=r"(r[3]) : "r"(addr));
}
__device__ __forceinline__ void mma16816(float* c, const uint32_t* a, const uint32_t* b) {
    asm volatile("mma.sync.aligned.m16n8k16.row.col.f32.f16.f16.f32 "
                 "{%0,%1,%2,%3}, {%4,%5,%6,%7}, {%8,%9}, {%0,%1,%2,%3};"
                 : "+f"(c[0]), "+f"(c[1]), "+f"(c[2]), "+f"(c[3])
                 : "r"(a[0]), "r"(a[1]), "r"(a[2]), "r"(a[3]), "r"(b[0]), "r"(b[1]));
}
__device__ __forceinline__ void cp16(uint32_t s, const void* g) {
    asm volatile("cp.async.cg.shared.global [%0], [%1], 16;" :: "r"(s), "l"(g));
}
__device__ __forceinline__ uint32_t smem_u32(const void* p) {
    return (uint32_t)__cvta_generic_to_shared(p);
}

// ---------------- precompute conversions ----------------
__global__ void convert_w_kernel(const float* __restrict__ Wq, const float* __restrict__ Wk,
                                 const float* __restrict__ Wv) {
    int idx = blockIdx.x * blockDim.x + threadIdx.x;
    if (idx >= NLAYER * DM * QKVW) return;
    int l = idx / (DM * QKVW);
    int r = idx - l * (DM * QKVW);
    int k = r / QKVW;
    int n = r - k * QKVW;
    int m = n >> 8;
    const float* W = (m == 0 ? Wq : (m == 1 ? Wk : Wv));
    g_wh[idx] = __float2half(W[l * DM * DM + k * DM + (n & 255)]);
}

// also zeroes pool/cnt (used only at layer 2 / tail, same stream)
__global__ void convert_x_kernel(const float* __restrict__ X) {
    int i4 = blockIdx.x * blockDim.x + threadIdx.x;
    if (i4 < NGRAPH * DM) g_pool[i4] = 0.f;
    if (i4 < NGRAPH) g_cnt[i4] = 0.f;
    if (i4 >= N_PAD * 64) return;
    int row = i4 >> 6;
    float4 f = make_float4(0.f, 0.f, 0.f, 0.f);
    if (row < N_NODES) f = ((const float4*)X)[i4];
    __half h[4];
    h[0] = __float2half(f.x); h[1] = __float2half(f.y);
    h[2] = __float2half(f.z); h[3] = __float2half(f.w);
    ((uint2*)g_xh)[i4] = *(uint2*)h;
}

// ---------------- CSR build (side stream) ----------------
__global__ void zero_deg_kernel() {
    int i = blockIdx.x * blockDim.x + threadIdx.x;
    if (i < N_NODES) g_deg[i] = 0;
}
__global__ void hist_kernel(const int* __restrict__ dst) {
    int e = blockIdx.x * blockDim.x + threadIdx.x;
    if (e < N_EDGES) atomicAdd(&g_deg[dst[e]], 1);
}
// multi-block scan: per-block inclusive scan -> exclusive write + block sums
__global__ void scan1_kernel() {
    __shared__ int sh[1024];
    int t = threadIdx.x, b = blockIdx.x;
    int i = b * 1024 + t;
    int v = (i < N_NODES) ? g_deg[i] : 0;
    sh[t] = v;
    __syncthreads();
    for (int off = 1; off < 1024; off <<= 1) {
        int x = sh[t];
        if (t >= off) x += sh[t - off];
        __syncthreads();
        sh[t] = x;
        __syncthreads();
    }
    if (i < N_NODES) g_rowptr[i] = sh[t] - v;     // block-local exclusive
    if (t == 1023) g_bsum[b] = sh[1023];
}
__global__ void scan2_kernel() {      // 1 thread: 30 elems
    if (threadIdx.x == 0) {
        int run = 0;
        for (int b = 0; b < SCAN_B; b++) { g_boff[b] = run; run += g_bsum[b]; }
        g_rowptr[N_NODES] = run;
    }
}
__global__ void scan3_kernel() {
    int i = blockIdx.x * blockDim.x + threadIdx.x;
    if (i >= N_NODES) return;
    int v = g_rowptr[i] + g_boff[i >> 10];
    g_rowptr[i] = v;
    g_wcnt[i] = v;
}
__global__ void scatter_kernel(const int* __restrict__ src, const int* __restrict__ dst,
                               const int* __restrict__ et) {
    int e = blockIdx.x * blockDim.x + threadIdx.x;
    if (e >= N_EDGES) return;
    int p = atomicAdd(&g_wcnt[dst[e]], 1);
    g_csr[p] = (src[e] << 3) | et[e];
}

// ---------------- tensor-core QKV GEMM (fp16, 128x128 tile, 4-stage) ----------------
__global__ __launch_bounds__(256, 2) void gemm_qkv_mma(
    int layer,
    const float* __restrict__ bq, const float* __restrict__ bk, const float* __restrict__ bv)
{
    extern __shared__ __align__(16) __half smem[];

    const int t = threadIdx.x, lane = t & 31, wid = t >> 5;
    const int warp_m = wid >> 2, warp_n = wid & 3;
    const int bm = blockIdx.x, by = blockIdx.y;       // by in [0,6)
    const __half* Wh = g_wh + (size_t)layer * DM * QKVW;

    float acc[4][4][4];
#pragma unroll
    for (int i = 0; i < 4; i++)
#pragma unroll
        for (int j = 0; j < 4; j++)
#pragma unroll
            for (int c = 0; c < 4; c++) acc[i][j][c] = 0.f;

    const int a_row0 = t >> 2,         a_cg0 = t & 3;
    const int a_row1 = (t + 256) >> 2, a_cg1 = t & 3;
    const int b_row0 = t >> 4,         b_cg0 = t & 15;
    const int b_row1 = (t + 256) >> 4, b_cg1 = t & 15;

#define CP_CHUNK(kc, s) do {                                                          \
        int k0 = (kc) * 32;                                                           \
        __half* st = smem + (s) * STAGE_E;                                            \
        cp16(smem_u32(st + a_row0 * ASTRIDE + a_cg0 * 8),                             \
             g_xh + (size_t)(bm * 128 + a_row0) * 256 + k0 + a_cg0 * 8);              \
        cp16(smem_u32(st + a_row1 * ASTRIDE + a_cg1 * 8),                             \
             g_xh + (size_t)(bm * 128 + a_row1) * 256 + k0 + a_cg1 * 8);              \
        cp16(smem_u32(st + OFF_BH + b_row0 * BSTRIDE + b_cg0 * 8),                    \
             Wh + (size_t)(k0 + b_row0) * QKVW + by * 128 + b_cg0 * 8);               \
        cp16(smem_u32(st + OFF_BH + b_row1 * BSTRIDE + b_cg1 * 8),                    \
             Wh + (size_t)(k0 + b_row1) * QKVW + by * 128 + b_cg1 * 8);               \
        asm volatile("cp.async.commit_group;");                                       \
    } while (0)

    CP_CHUNK(0, 0);
    CP_CHUNK(1, 1);

    const int g = lane >> 3, ri = lane & 7;
    const uint32_t sb0 = smem_u32(smem);

    for (int kc = 0; kc < 8; kc++) {
        if (kc < 6) {
            CP_CHUNK(kc + 2, (kc + 2) & 3);
            asm volatile("cp.async.wait_group 2;" ::: "memory");
        } else if (kc == 6) {
            asm volatile("cp.async.wait_group 1;" ::: "memory");
        } else {
            asm volatile("cp.async.wait_group 0;" ::: "memory");
        }
        __syncthreads();

        const uint32_t base = sb0 + (uint32_t)((kc & 3) * STAGE_E * 2);

#pragma unroll
        for (int ks = 0; ks < 32; ks += 16) {
            uint32_t af[4][4];
#pragma unroll
            for (int mt = 0; mt < 4; mt++) {
                uint32_t eoff = (uint32_t)((warp_m * 64 + mt * 16 + (g & 1) * 8 + ri) * ASTRIDE
                                           + ks + (g >> 1) * 8) * 2u;
                ldsm4(af[mt], base + eoff);
            }
            uint32_t bfh[4][2];
#pragma unroll
            for (int ntp = 0; ntp < 2; ntp++) {
                uint32_t boff = (uint32_t)((ks + (g & 1) * 8 + ri) * BSTRIDE
                                           + warp_n * 32 + ntp * 16 + (g >> 1) * 8) * 2u;
                uint32_t r[4];
                ldsm4t(r, base + OFF_BH * 2 + boff);
                bfh[ntp * 2][0] = r[0]; bfh[ntp * 2][1] = r[1];
                bfh[ntp * 2 + 1][0] = r[2]; bfh[ntp * 2 + 1][1] = r[3];
            }
#pragma unroll
            for (int mt = 0; mt < 4; mt++)
#pragma unroll
                for (int nt = 0; nt < 4; nt++)
                    mma16816(acc[mt][nt], af[mt], bfh[nt]);
        }
    }

    const int sec = by >> 1;                          // 0=q, 1=k, 2=v
    const float* bias = sec == 0 ? bq : (sec == 1 ? bk : bv);
    const int lcol = (by & 1) * 128;
#pragma unroll
    for (int mt = 0; mt < 4; mt++)
#pragma unroll
        for (int nt = 0; nt < 4; nt++) {
            int r0 = bm * 128 + warp_m * 64 + mt * 16 + (lane >> 2);
            int ocol = warp_n * 32 + nt * 8 + (lane & 3) * 2;
            float b0 = bias[lcol + ocol], b1 = bias[lcol + ocol + 1];
            if (sec == 0) {
                if (r0 < N_NODES)
                    *(float2*)(g_q + (size_t)r0 * DM + lcol + ocol) =
                        make_float2(acc[mt][nt][0] + b0, acc[mt][nt][1] + b1);
                if (r0 + 8 < N_NODES)
                    *(float2*)(g_q + (size_t)(r0 + 8) * DM + lcol + ocol) =
                        make_float2(acc[mt][nt][2] + b0, acc[mt][nt][3] + b1);
            } else {
                size_t cbase = (size_t)(sec - 1) * 256 + lcol + ocol;
                if (r0 < N_NODES)
                    *(__half2*)(g_kv + (size_t)r0 * 512 + cbase) =
                        __floats2half2_rn(acc[mt][nt][0] + b0, acc[mt][nt][1] + b1);
                if (r0 + 8 < N_NODES)
                    *(__half2*)(g_kv + (size_t)(r0 + 8) * 512 + cbase) =
                        __floats2half2_rn(acc[mt][nt][2] + b0, acc[mt][nt][3] + b1);
            }
        }
#undef CP_CHUNK
}

// ---------------- fused attention: warp/dst, online softmax + ELU; 2x unrolled ----------
__global__ __launch_bounds__(256) void attn_kernel(const float* __restrict__ Ee,
                                                   const int* __restrict__ batch, int final_l)
{
    int d = (blockIdx.x * blockDim.x + threadIdx.x) >> 5;
    if (d >= N_NODES) return;
    int lane = threadIdx.x & 31;

    const float4* qp = (const float4*)(g_q + (size_t)d * DM) + lane * 2;
    float4 q0 = qp[0], q1 = qp[1];

    int e0i = g_rowptr[d], e1i = g_rowptr[d + 1];
    float m = -1e30f, den = 0.f;
    float acc[8];
#pragma unroll
    for (int j = 0; j < 8; j++) acc[j] = 0.f;

    int e = e0i;
    for (; e + 2 <= e1i; e += 2) {
        int p0 = g_csr[e], p1 = g_csr[e + 1];
        int s0 = p0 >> 3, ty0 = p0 & 7;
        int s1 = p1 >> 3, ty1 = p1 & 7;
        uint4 k0r = *(const uint4*)(g_kv + (size_t)s0 * 512 + lane * 8);
        uint4 v0r = *(const uint4*)(g_kv + (size_t)s0 * 512 + 256 + lane * 8);
        uint4 k1r = *(const uint4*)(g_kv + (size_t)s1 * 512 + lane * 8);
        uint4 v1r = *(const uint4*)(g_kv + (size_t)s1 * 512 + 256 + lane * 8);
        const float4* e0p = (const float4*)(Ee + ty0 * 256) + lane * 2;
        const float4* e1p = (const float4*)(Ee + ty1 * 256) + lane * 2;
        float4 ea0 = e0p[0], ea1 = e0p[1];
        float4 eb0 = e1p[0], eb1 = e1p[1];

        float ke0[8], ve0[8], ke1[8], ve1[8];
        {
            float2 kf[4], vf[4];
            kf[0] = __half22float2(*(__half2*)&k0r.x); kf[1] = __half22float2(*(__half2*)&k0r.y);
            kf[2] = __half22float2(*(__half2*)&k0r.z); kf[3] = __half22float2(*(__half2*)&k0r.w);
            vf[0] = __half22float2(*(__half2*)&v0r.x); vf[1] = __half22float2(*(__half2*)&v0r.y);
            vf[2] = __half22float2(*(__half2*)&v0r.z); vf[3] = __half22float2(*(__half2*)&v0r.w);
            ke0[0]=kf[0].x+ea0.x; ke0[1]=kf[0].y+ea0.y; ke0[2]=kf[1].x+ea0.z; ke0[3]=kf[1].y+ea0.w;
            ke0[4]=kf[2].x+ea1.x; ke0[5]=kf[2].y+ea1.y; ke0[6]=kf[3].x+ea1.z; ke0[7]=kf[3].y+ea1.w;
            ve0[0]=vf[0].x+ea0.x; ve0[1]=vf[0].y+ea0.y; ve0[2]=vf[1].x+ea0.z; ve0[3]=vf[1].y+ea0.w;
            ve0[4]=vf[2].x+ea1.x; ve0[5]=vf[2].y+ea1.y; ve0[6]=vf[3].x+ea1.z; ve0[7]=vf[3].y+ea1.w;
        }
        {
            float2 kf[4], vf[4];
            kf[0] = __half22float2(*(__half2*)&k1r.x); kf[1] = __half22float2(*(__half2*)&k1r.y);
            kf[2] = __half22float2(*(__half2*)&k1r.z); kf[3] = __half22float2(*(__half2*)&k1r.w);
            vf[0] = __half22float2(*(__half2*)&v1r.x); vf[1] = __half22float2(*(__half2*)&v1r.y);
            vf[2] = __half22float2(*(__half2*)&v1r.z); vf[3] = __half22float2(*(__half2*)&v1r.w);
            ke1[0]=kf[0].x+eb0.x; ke1[1]=kf[0].y+eb0.y; ke1[2]=kf[1].x+eb0.z; ke1[3]=kf[1].y+eb0.w;
            ke1[4]=kf[2].x+eb1.x; ke1[5]=kf[2].y+eb1.y; ke1[6]=kf[3].x+eb1.z; ke1[7]=kf[3].y+eb1.w;
            ve1[0]=vf[0].x+eb0.x; ve1[1]=vf[0].y+eb0.y; ve1[2]=vf[1].x+eb0.z; ve1[3]=vf[1].y+eb0.w;
            ve1[4]=vf[2].x+eb1.x; ve1[5]=vf[2].y+eb1.y; ve1[6]=vf[3].x+eb1.z; ve1[7]=vf[3].y+eb1.w;
        }

        float pa = q0.x*ke0[0]+q0.y*ke0[1]+q0.z*ke0[2]+q0.w*ke0[3]
                 + q1.x*ke0[4]+q1.y*ke0[5]+q1.z*ke0[6]+q1.w*ke0[7];
        float pb = q0.x*ke1[0]+q0.y*ke1[1]+q0.z*ke1[2]+q0.w*ke1[3]
                 + q1.x*ke1[4]+q1.y*ke1[5]+q1.z*ke1[6]+q1.w*ke1[7];
        pa += __shfl_xor_sync(0xffffffffu, pa, 1, 8);
        pb += __shfl_xor_sync(0xffffffffu, pb, 1, 8);
        pa += __shfl_xor_sync(0xffffffffu, pa, 2, 8);
        pb += __shfl_xor_sync(0xffffffffu, pb, 2, 8);
        pa += __shfl_xor_sync(0xffffffffu, pa, 4, 8);
        pb += __shfl_xor_sync(0xffffffffu, pb, 4, 8);
        float sc0 = pa * 0.125f, sc1 = pb * 0.125f;

        float mn = fmaxf(m, sc0);
        float scale = __expf(m - mn);
        float w = __expf(sc0 - mn);
        den = den * scale + w;
#pragma unroll
        for (int j = 0; j < 8; j++) acc[j] = acc[j] * scale + w * ve0[j];
        m = mn;

        mn = fmaxf(m, sc1);
        scale = __expf(m - mn);
        w = __expf(sc1 - mn);
        den = den * scale + w;
#pragma unroll
        for (int j = 0; j < 8; j++) acc[j] = acc[j] * scale + w * ve1[j];
        m = mn;
    }
    if (e < e1i) {
        int p0 = g_csr[e];
        int s0 = p0 >> 3, ty0 = p0 & 7;
        uint4 k0r = *(const uint4*)(g_kv + (size_t)s0 * 512 + lane * 8);
        uint4 v0r = *(const uint4*)(g_kv + (size_t)s0 * 512 + 256 + lane * 8);
        const float4* e0p = (const float4*)(Ee + ty0 * 256) + lane * 2;
        float4 ea0 = e0p[0], ea1 = e0p[1];
        float2 kf[4], vf[4];
        kf[0] = __half22float2(*(__half2*)&k0r.x); kf[1] = __half22float2(*(__half2*)&k0r.y);
        kf[2] = __half22float2(*(__half2*)&k0r.z); kf[3] = __half22float2(*(__half2*)&k0r.w);
        vf[0] = __half22float2(*(__half2*)&v0r.x); vf[1] = __half22float2(*(__half2*)&v0r.y);
        vf[2] = __half22float2(*(__half2*)&v0r.z); vf[3] = __half22float2(*(__half2*)&v0r.w);
        float ke0[8], ve0[8];
        ke0[0]=kf[0].x+ea0.x; ke0[1]=kf[0].y+ea0.y; ke0[2]=kf[1].x+ea0.z; ke0[3]=kf[1].y+ea0.w;
        ke0[4]=kf[2].x+ea1.x; ke0[5]=kf[2].y+ea1.y; ke0[6]=kf[3].x+ea1.z; ke0[7]=kf[3].y+ea1.w;
        ve0[0]=vf[0].x+ea0.x; ve0[1]=vf[0].y+ea0.y; ve0[2]=vf[1].x+ea0.z; ve0[3]=vf[1].y+ea0.w;
        ve0[4]=vf[2].x+ea1.x; ve0[5]=vf[2].y+ea1.y; ve0[6]=vf[3].x+ea1.z; ve0[7]=vf[3].y+ea1.w;
        float pa = q0.x*ke0[0]+q0.y*ke0[1]+q0.z*ke0[2]+q0.w*ke0[3]
                 + q1.x*ke0[4]+q1.y*ke0[5]+q1.z*ke0[6]+q1.w*ke0[7];
        pa += __shfl_xor_sync(0xffffffffu, pa, 1, 8);
        pa += __shfl_xor_sync(0xffffffffu, pa, 2, 8);
        pa += __shfl_xor_sync(0xffffffffu, pa, 4, 8);
        float sc0 = pa * 0.125f;
        float mn = fmaxf(m, sc0);
        float scale = __expf(m - mn);
        float w = __expf(sc0 - mn);
        den = den * scale + w;
#pragma unroll
        for (int j = 0; j < 8; j++) acc[j] = acc[j] * scale + w * ve0[j];
        m = mn;
    }

    float inv = den > 0.f ? 1.f / den : 0.f;
    float o[8];
#pragma unroll
    for (int j = 0; j < 8; j++) {
        float v = acc[j] * inv;
        o[j] = v > 0.f ? v : expm1f(v);
    }
    if (final_l) {
        int b = batch[d];
        float* p = g_pool + (size_t)b * DM + lane * 8;
        red_add_v4(p,     make_float4(o[0], o[1], o[2], o[3]));
        red_add_v4(p + 4, make_float4(o[4], o[5], o[6], o[7]));
        if (lane == 0) atomicAdd(&g_cnt[b], 1.0f);
    } else {
        __half h[8];
#pragma unroll
        for (int j = 0; j < 8; j++) h[j] = __float2half(o[j]);
        *(uint4*)(g_xh + (size_t)d * DM + lane * 8) = *(uint4*)h;
    }
}

// ---------------- GRU + FC ----------------
__global__ void gru_fc(const float* __restrict__ W_ih, const float* __restrict__ b_ih,
                       const float* __restrict__ b_hh,
                       const float* __restrict__ W_fc, const float* __restrict__ b_fc,
                       float* __restrict__ out)
{
    __shared__ float gsh[256];
    __shared__ float gish[192];
    __shared__ float hsh[64];
    int b = blockIdx.x;
    int t = threadIdx.x;
    float inv = 1.0f / fmaxf(g_cnt[b], 1.0f);
    gsh[t] = g_pool[b * DM + t] * inv;
    __syncthreads();
    if (t < 192) {
        float s = b_ih[t];
        const float* w = W_ih + t * 256;
#pragma unroll 8
        for (int k = 0; k < 256; k++) s += gsh[k] * w[k];
        gish[t] = s;
    }
    __syncthreads();
    if (t < 64) {
        float r = 1.f / (1.f + expf(-(gish[t] + b_hh[t])));
        float z = 1.f / (1.f + expf(-(gish[64 + t] + b_hh[64 + t])));
        float n = tanhf(gish[128 + t] + r * b_hh[128 + t]);
        hsh[t] = (1.f - z) * n;
    }
    __syncthreads();
    if (t < 2) {
        float s = b_fc[t];
        const float* w = W_fc + t * 64;
#pragma unroll
        for (int k = 0; k < 64; k++) s += hsh[k] * w[k];
        out[b * 2 + t] = s;
    }
}

// ---------------- launch ----------------
extern "C" void kernel_launch(void* const* d_in, const int* in_sizes, int n_in,
                              void* d_out, int out_size)
{
    const float* x     = (const float*)d_in[0];
    const int*   eidx  = (const int*)d_in[1];
    const int*   batch = (const int*)d_in[2];
    const int*   etid  = (const int*)d_in[3];
    const float* Wq    = (const float*)d_in[4];
    const float* bq    = (const float*)d_in[5];
    const float* Wk    = (const float*)d_in[6];
    const float* bk    = (const float*)d_in[7];
    const float* Wv    = (const float*)d_in[8];
    const float* bv    = (const float*)d_in[9];
    const float* Ee    = (const float*)d_in[10];
    const float* W_ih  = (const float*)d_in[11];
    const float* b_ih  = (const float*)d_in[12];
    const float* b_hh  = (const float*)d_in[14];
    const float* W_fc  = (const float*)d_in[15];
    const float* b_fc  = (const float*)d_in[16];

    const int* src = eidx;
    const int* dst = eidx + N_EDGES;

    static int init_done = 0;
    static cudaStream_t s_side;
    static cudaEvent_t ev_fork, ev_join;
    const int gemm_smem = 4 * STAGE_E * (int)sizeof(__half);   // 75776 B
    if (!init_done) {
        cudaFuncSetAttribute(gemm_qkv_mma, cudaFuncAttributeMaxDynamicSharedMemorySize, gemm_smem);
        cudaStreamCreateWithFlags(&s_side, cudaStreamNonBlocking);
        cudaEventCreateWithFlags(&ev_fork, cudaEventDisableTiming);
        cudaEventCreateWithFlags(&ev_join, cudaEventDisableTiming);
        init_done = 1;
    }

    // fork: CSR build runs on s_side concurrently with convert + gemm(0)
    cudaEventRecord(ev_fork, 0);
    cudaStreamWaitEvent(s_side, ev_fork, 0);

    zero_deg_kernel<<<(N_NODES + 255) / 256, 256, 0, s_side>>>();
    hist_kernel<<<(N_EDGES + 255) / 256, 256, 0, s_side>>>(dst);
    scan1_kernel<<<SCAN_B, 1024, 0, s_side>>>();
    scan2_kernel<<<1, 32, 0, s_side>>>();
    scan3_kernel<<<(N_NODES + 255) / 256, 256, 0, s_side>>>();
    scatter_kernel<<<(N_EDGES + 255) / 256, 256, 0, s_side>>>(src, dst, etid);
    cudaEventRecord(ev_join, s_side);

    convert_w_kernel<<<(NLAYER * DM * QKVW + 255) / 256, 256>>>(Wq, Wk, Wv);
    convert_x_kernel<<<(N_PAD * 64 + 255) / 256, 256>>>(x);   // also zeroes pool/cnt

    dim3 ggrid(N_PAD / 128, 6);
    for (int l = 0; l < NLAYER; l++) {
        gemm_qkv_mma<<<ggrid, 256, gemm_smem>>>(l, bq + l * DM, bk + l * DM, bv + l * DM);
        if (l == 0) cudaStreamWaitEvent(0, ev_join, 0);   // CSR ready before attn(0)
        attn_kernel<<<(N_NODES * 32 + 255) / 256, 256>>>(Ee + l * 8 * DM, batch,
                                                         l == NLAYER - 1 ? 1 : 0);
    }
    gru_fc<<<NGRAPH, 256>>>(W_ih, b_ih, b_hh, W_fc, b_fc, (float*)d_out);
}